// round 7
// baseline (speedup 1.0000x reference)
#include <cuda_runtime.h>
#include <cuda_bf16.h>
#include <cstdint>

#define F 128
#define RCUT 5.0f
#define NODE_BLOCK 320          // 10 warps
#define TILE_NODES 80           // 10 warps * 8 nodes
#define NODE_GRID 304           // persistent, 2 CTAs/SM
#define MAX_NODES 100000

// Scratch (allocation-free rule: __device__ globals)
__device__ float  q_dev[MAX_NODES];
__device__ float4 mu4_dev[MAX_NODES];

// ---------- f32x2 packed helpers (sm_100+) ----------
static __device__ __forceinline__ unsigned long long pack2(float lo, float hi) {
    unsigned long long r;
    asm("mov.b64 %0, {%1, %2};" : "=l"(r) : "f"(lo), "f"(hi));
    return r;
}
static __device__ __forceinline__ void unpack2(unsigned long long v, float& lo, float& hi) {
    asm("mov.b64 {%0, %1}, %2;" : "=f"(lo), "=f"(hi) : "l"(v));
}
static __device__ __forceinline__ unsigned long long fma2(unsigned long long a,
                                                          unsigned long long b,
                                                          unsigned long long c) {
    unsigned long long d;
    asm("fma.rn.f32x2 %0, %1, %2, %3;" : "=l"(d) : "l"(a), "l"(b), "l"(c));
    return d;
}
static __device__ __forceinline__ unsigned long long add2(unsigned long long a,
                                                          unsigned long long b) {
    unsigned long long d;
    asm("add.rn.f32x2 %0, %1, %2;" : "=l"(d) : "l"(a), "l"(b));
    return d;
}
static __device__ __forceinline__ float silu_f(float z) {
    return __fdividef(z, 1.0f + __expf(-z));
}

// ---------- Kernel 1: node MLP -> q (also zeroes mu4 scratch) ----------
// Outer-product register blocking: thread = (lane tx -> 4 features, warp -> 8 nodes).
// Per k2 step: 2 LDS.128 (weights, conflict-free) + 4 broadcast LDS.128 (x pairs)
// feed 32 fma.rn.f32x2 -> FMA-pipe bound instead of smem-crossbar bound.
__global__ void __launch_bounds__(NODE_BLOCK, 2)
node_q_kernel(const float* __restrict__ x, const float* __restrict__ W1,
              const float* __restrict__ b1, const float* __restrict__ W2,
              const float* __restrict__ b2, int n_nodes) {
    extern __shared__ float smem[];
    float*  W1s = smem;                       // 128*128 floats = 64 KB, [k][f]
    float4* xs4 = (float4*)(smem + F * F);    // 40 pairs * 64 k2 = 2560 float4 = 40 KB

    const int tid = threadIdx.x;
    const int wid = tid >> 5;     // 0..9  -> node subtile
    const int tx  = tid & 31;     // lane  -> feature group f = 4*tx + fl

    // Zero the accumulation scratch (edge kernel runs after us -> ordered)
    for (int i = blockIdx.x * NODE_BLOCK + tid; i < n_nodes; i += gridDim.x * NODE_BLOCK)
        mu4_dev[i] = make_float4(0.f, 0.f, 0.f, 0.f);

    // Stage W1 (row-major [k][f], exactly the global layout)
    {
        const float4* g = (const float4*)W1;
        float4* s = (float4*)W1s;
        for (int i = tid; i < (F * F) / 4; i += NODE_BLOCK) s[i] = g[i];
    }
    const float4 b1v = ((const float4*)b1)[tx];   // b1[4tx..4tx+3]
    const float4 w2v = ((const float4*)W2)[tx];   // W2[4tx..4tx+3]
    const float  b2v = b2[0];
    __syncthreads();

    const int n_tiles = n_nodes / TILE_NODES;  // 100000 / 80 = 1250, exact
    for (int tile = blockIdx.x; tile < n_tiles; tile += gridDim.x) {
        const int base = tile * TILE_NODES;

        // Stage x tile, node-pair-interleaved: xs4[p_glob*64 + k2] =
        //   (x[n2p,k], x[n2p+1,k], x[n2p,k+1], x[n2p+1,k+1]),  p_glob = 0..39
        for (int i = tid; i < 40 * (F / 2); i += NODE_BLOCK) {
            const int p  = i >> 6;   // global pair 0..39
            const int k2 = i & 63;
            const float2 a = *(const float2*)(x + (size_t)(base + 2 * p)     * F + 2 * k2);
            const float2 b = *(const float2*)(x + (size_t)(base + 2 * p + 1) * F + 2 * k2);
            xs4[i] = make_float4(a.x, b.x, a.y, b.y);
        }
        __syncthreads();

        // acc[fl][p] : feature 4tx+fl  x  node pair p (f32x2 over the 2 nodes)
        unsigned long long acc[4][4];
        #pragma unroll
        for (int p = 0; p < 4; p++) {
            acc[0][p] = pack2(b1v.x, b1v.x);
            acc[1][p] = pack2(b1v.y, b1v.y);
            acc[2][p] = pack2(b1v.z, b1v.z);
            acc[3][p] = pack2(b1v.w, b1v.w);
        }

        const ulonglong2* xw = (const ulonglong2*)(xs4 + wid * 4 * (F / 2));
        #pragma unroll 2
        for (int k2 = 0; k2 < F / 2; k2++) {
            const float4 wa = *(const float4*)(W1s + (2 * k2)     * F + 4 * tx);
            const float4 wb = *(const float4*)(W1s + (2 * k2 + 1) * F + 4 * tx);
            const unsigned long long w0[4] = {pack2(wa.x, wa.x), pack2(wa.y, wa.y),
                                              pack2(wa.z, wa.z), pack2(wa.w, wa.w)};
            const unsigned long long w1[4] = {pack2(wb.x, wb.x), pack2(wb.y, wb.y),
                                              pack2(wb.z, wb.z), pack2(wb.w, wb.w)};
            #pragma unroll
            for (int p = 0; p < 4; p++) {
                const ulonglong2 xv = xw[p * (F / 2) + k2];  // broadcast LDS.128
                #pragma unroll
                for (int fl = 0; fl < 4; fl++)
                    acc[fl][p] = fma2(xv.x, w0[fl], acc[fl][p]);
                #pragma unroll
                for (int fl = 0; fl < 4; fl++)
                    acc[fl][p] = fma2(xv.y, w1[fl], acc[fl][p]);
            }
        }

        // silu(h) * W2[f], then sum the 4 local features
        unsigned long long tot[4];
        #pragma unroll
        for (int p = 0; p < 4; p++) {
            float h0, h1;
            unsigned long long c0, c1, c2, c3;
            unpack2(acc[0][p], h0, h1); c0 = pack2(silu_f(h0) * w2v.x, silu_f(h1) * w2v.x);
            unpack2(acc[1][p], h0, h1); c1 = pack2(silu_f(h0) * w2v.y, silu_f(h1) * w2v.y);
            unpack2(acc[2][p], h0, h1); c2 = pack2(silu_f(h0) * w2v.z, silu_f(h1) * w2v.z);
            unpack2(acc[3][p], h0, h1); c3 = pack2(silu_f(h0) * w2v.w, silu_f(h1) * w2v.w);
            tot[p] = add2(add2(c0, c1), add2(c2, c3));
        }

        // Butterfly over the 32 lanes (remaining feature dimension).
        // Warp owns its 8 nodes exclusively -> no cross-warp reduction needed.
        #pragma unroll
        for (int off = 16; off > 0; off >>= 1) {
            #pragma unroll
            for (int p = 0; p < 4; p++) {
                unsigned long long o = __shfl_xor_sync(0xffffffffu, tot[p], off);
                tot[p] = add2(tot[p], o);
            }
        }
        if (tx == 0) {
            const int nb = base + wid * 8;
            #pragma unroll
            for (int p = 0; p < 4; p++) {
                float a, b;
                unpack2(tot[p], a, b);
                q_dev[nb + 2 * p]     = silu_f(a + b2v);
                q_dev[nb + 2 * p + 1] = silu_f(b + b2v);
            }
        }
        __syncthreads();  // protect xs4 before next tile's staging
    }
}

// ---------- Kernel 2: edge pass, 4 edges/thread, vectorized LSU traffic ----
__global__ void __launch_bounds__(256)
edge_kernel4(const float4* __restrict__ rij4, const float4* __restrict__ vij4,
             const int4* __restrict__ src4, const int4* __restrict__ dst4,
             int n_quads) {
    const int i = blockIdx.x * blockDim.x + threadIdx.x;
    if (i >= n_quads) return;

    const float4 r = rij4[i];
    const int4   s = src4[i];
    const int4   d = dst4[i];
    const float4 a = vij4[(size_t)3 * i];
    const float4 b = vij4[(size_t)3 * i + 1];
    const float4 c = vij4[(size_t)3 * i + 2];

    const float k = 3.14159265358979323846f / RCUT;
    float c0 = 0.5f * (__cosf(r.x * k) + 1.0f); if (r.x >= RCUT) c0 = 0.0f;
    float c1 = 0.5f * (__cosf(r.y * k) + 1.0f); if (r.y >= RCUT) c1 = 0.0f;
    float c2 = 0.5f * (__cosf(r.z * k) + 1.0f); if (r.z >= RCUT) c2 = 0.0f;
    float c3 = 0.5f * (__cosf(r.w * k) + 1.0f); if (r.w >= RCUT) c3 = 0.0f;

    const float s0 = __ldg(&q_dev[s.x]) * c0;
    const float s1 = __ldg(&q_dev[s.y]) * c1;
    const float s2 = __ldg(&q_dev[s.z]) * c2;
    const float s3 = __ldg(&q_dev[s.w]) * c3;

    atomicAdd(&mu4_dev[d.x], make_float4(a.x * s0, a.y * s0, a.z * s0, 0.0f));
    atomicAdd(&mu4_dev[d.y], make_float4(a.w * s1, b.x * s1, b.y * s1, 0.0f));
    atomicAdd(&mu4_dev[d.z], make_float4(b.z * s2, b.w * s2, c.x * s2, 0.0f));
    atomicAdd(&mu4_dev[d.w], make_float4(c.y * s3, c.z * s3, c.w * s3, 0.0f));
}

// ---------- Kernel 3: compact [N,4] scratch -> [N,3] output, 4 nodes/thread --
__global__ void copy_kernel4(float4* __restrict__ out4, int n_quads) {
    const int i = blockIdx.x * blockDim.x + threadIdx.x;
    if (i >= n_quads) return;
    const float4 m0 = mu4_dev[4 * i];
    const float4 m1 = mu4_dev[4 * i + 1];
    const float4 m2 = mu4_dev[4 * i + 2];
    const float4 m3 = mu4_dev[4 * i + 3];
    out4[3 * i]     = make_float4(m0.x, m0.y, m0.z, m1.x);
    out4[3 * i + 1] = make_float4(m1.y, m1.z, m2.x, m2.y);
    out4[3 * i + 2] = make_float4(m2.z, m3.x, m3.y, m3.z);
}

extern "C" void kernel_launch(void* const* d_in, const int* in_sizes, int n_in,
                              void* d_out, int out_size) {
    const float* x   = (const float*)d_in[0];
    const float* rij = (const float*)d_in[1];
    const float* vij = (const float*)d_in[2];
    const int*   src = (const int*)d_in[3];
    const int*   dst = (const int*)d_in[4];
    const float* W1  = (const float*)d_in[5];
    const float* b1  = (const float*)d_in[6];
    const float* W2  = (const float*)d_in[7];
    const float* b2  = (const float*)d_in[8];
    float* out = (float*)d_out;

    const int n_nodes = in_sizes[0] / F;   // 100000
    const int n_edges = in_sizes[1];       // 6400000

    const int smem_bytes = F * F * 4 + 40 * (F / 2) * 16;  // 64KB + 40KB = 106496
    cudaFuncSetAttribute(node_q_kernel,
                         cudaFuncAttributeMaxDynamicSharedMemorySize, smem_bytes);

    node_q_kernel<<<NODE_GRID, NODE_BLOCK, smem_bytes>>>(x, W1, b1, W2, b2, n_nodes);

    const int eq = n_edges / 4;            // 1,600,000 (exact)
    edge_kernel4<<<(eq + 255) / 256, 256>>>((const float4*)rij, (const float4*)vij,
                                            (const int4*)src, (const int4*)dst, eq);

    const int nq = n_nodes / 4;            // 25,000 (exact)
    copy_kernel4<<<(nq + 255) / 256, 256>>>((float4*)out, nq);
}

// round 11
// speedup vs baseline: 1.3718x; 1.3718x over previous
#include <cuda_runtime.h>
#include <cuda_bf16.h>
#include <cstdint>

#define F 128
#define RCUT 5.0f
#define MAX_NODES 100000

// Scratch (allocation-free rule: __device__ globals)
__device__ float  q_dev[MAX_NODES];
__device__ float4 mu4_dev[MAX_NODES];
// Transposed split-bf16 W1 images: W1T[f][k], dense [128][128] bf16
__device__ __align__(16) unsigned char W1T_hi[32768];
__device__ __align__(16) unsigned char W1T_lo[32768];

static __device__ __forceinline__ float silu_f(float z) {
    return __fdividef(z, 1.0f + __expf(-z));
}
static __device__ __forceinline__ uint32_t bpack(__nv_bfloat16 lo, __nv_bfloat16 hi) {
    return (uint32_t)__bfloat16_as_ushort(lo) | ((uint32_t)__bfloat16_as_ushort(hi) << 16);
}

// warp-level bf16 MMA, baseline ISA (works on plain sm_103 target)
static __device__ __forceinline__ void mma16816(float* d, const uint32_t* a,
                                                uint32_t b0, uint32_t b1) {
    asm volatile(
        "mma.sync.aligned.m16n8k16.row.col.f32.bf16.bf16.f32 "
        "{%0,%1,%2,%3}, {%4,%5,%6,%7}, {%8,%9}, {%0,%1,%2,%3};"
        : "+f"(d[0]), "+f"(d[1]), "+f"(d[2]), "+f"(d[3])
        : "r"(a[0]), "r"(a[1]), "r"(a[2]), "r"(a[3]), "r"(b0), "r"(b1));
}

// ---------- Kernel 0: W1 -> transposed split-bf16 images ----------
// 16 blocks x 128 threads. Block b covers k-rows 8b..8b+7; thread = feature f.
__global__ void prep_B_kernel(const float* __restrict__ W1) {
    const int f = threadIdx.x;
    const int b = blockIdx.x;
    uint32_t hi[4], lo[4];
    #pragma unroll
    for (int j = 0; j < 4; j++) {
        const float w0 = W1[(8 * b + 2 * j)     * F + f];
        const float w1 = W1[(8 * b + 2 * j + 1) * F + f];
        const __nv_bfloat16 h0 = __float2bfloat16_rn(w0);
        const __nv_bfloat16 h1 = __float2bfloat16_rn(w1);
        const __nv_bfloat16 l0 = __float2bfloat16_rn(w0 - __bfloat162float(h0));
        const __nv_bfloat16 l1 = __float2bfloat16_rn(w1 - __bfloat162float(h1));
        hi[j] = bpack(h0, h1);
        lo[j] = bpack(l0, l1);
    }
    *(uint4*)(W1T_hi + f * 256 + b * 16) = make_uint4(hi[0], hi[1], hi[2], hi[3]);
    *(uint4*)(W1T_lo + f * 256 + b * 16) = make_uint4(lo[0], lo[1], lo[2], lo[3]);
}

// ---------- Kernel 1: node MLP via mma.sync split-bf16; also zeroes mu4 -----
// CTA = 256 thr / 8 warps, 128 nodes. Warp (mi = wid&3, nj = wid>>2):
// 32-node x 64-feature tile. 3 passes accumulate h = x@W1 in fp32 frags.
// Padded smem rows (272 B) make all fragment LDS conflict-free.
#define PADB 272
#define SM_AH  0
#define SM_AL  34816
#define SM_BH  69632
#define SM_BL  104448
#define SM_B1  139264
#define SM_W2  139776
#define SM_RED 140288
#define SM_TOT 141312

__global__ void __launch_bounds__(256)
node_q_kernel(const float* __restrict__ x, const float* __restrict__ b1,
              const float* __restrict__ W2, const float* __restrict__ b2,
              int n_nodes) {
    extern __shared__ __align__(16) unsigned char smem[];
    const int tid  = threadIdx.x;
    const int wid  = tid >> 5;
    const int lane = tid & 31;
    const int g    = lane >> 2;   // row within 8-row group
    const int qp   = lane & 3;    // quad position -> k/col pairs
    const int mi   = wid & 3;     // 32-node subtile
    const int nj   = wid >> 2;    // 64-feature half
    const int base = blockIdx.x * 128;

    // Zero accumulation scratch (edge kernel is ordered after us)
    for (int i = blockIdx.x * 256 + tid; i < n_nodes; i += gridDim.x * 256)
        mu4_dev[i] = make_float4(0.f, 0.f, 0.f, 0.f);

    // ---- Stage x tile -> split bf16, padded rows ----
    for (int i = tid; i < 4096; i += 256) {
        const int row = i >> 5;
        const int c4  = i & 31;
        const int col = 4 * c4;
        float4 v = make_float4(0.f, 0.f, 0.f, 0.f);
        if (base + row < n_nodes)
            v = ((const float4*)(x + (size_t)(base + row) * F))[c4];
        const __nv_bfloat16 h0 = __float2bfloat16_rn(v.x);
        const __nv_bfloat16 h1 = __float2bfloat16_rn(v.y);
        const __nv_bfloat16 h2 = __float2bfloat16_rn(v.z);
        const __nv_bfloat16 h3 = __float2bfloat16_rn(v.w);
        const __nv_bfloat16 l0 = __float2bfloat16_rn(v.x - __bfloat162float(h0));
        const __nv_bfloat16 l1 = __float2bfloat16_rn(v.y - __bfloat162float(h1));
        const __nv_bfloat16 l2 = __float2bfloat16_rn(v.z - __bfloat162float(h2));
        const __nv_bfloat16 l3 = __float2bfloat16_rn(v.w - __bfloat162float(h3));
        const int off = row * PADB + col * 2;
        *(uint2*)(smem + SM_AH + off) = make_uint2(bpack(h0, h1), bpack(h2, h3));
        *(uint2*)(smem + SM_AL + off) = make_uint2(bpack(l0, l1), bpack(l2, l3));
    }
    // ---- Copy W1T images into padded smem ----
    for (int i = tid; i < 4096; i += 256) {
        const int row = i >> 5;
        const int c4  = i & 31;
        const int col = 4 * c4;
        const int goff = row * 256 + col * 2;
        const int soff = row * PADB + col * 2;
        *(uint2*)(smem + SM_BH + soff) = *(const uint2*)(W1T_hi + goff);
        *(uint2*)(smem + SM_BL + soff) = *(const uint2*)(W1T_lo + goff);
    }
    if (tid < 128) {
        ((float*)(smem + SM_B1))[tid] = b1[tid];
        ((float*)(smem + SM_W2))[tid] = W2[tid];
    }
    __syncthreads();

    // ---- 3-pass MMA: h = xh@Wh + xh@Wl + xl@Wh ----
    float acc[2][8][4];
    #pragma unroll
    for (int mc = 0; mc < 2; mc++)
        #pragma unroll
        for (int nc = 0; nc < 8; nc++)
            #pragma unroll
            for (int r = 0; r < 4; r++) acc[mc][nc][r] = 0.0f;

    #pragma unroll
    for (int pass = 0; pass < 3; pass++) {
        const unsigned char* As = smem + ((pass == 2) ? SM_AL : SM_AH);
        const unsigned char* Bs = smem + ((pass == 1) ? SM_BL : SM_BH);
        #pragma unroll
        for (int kc = 0; kc < 8; kc++) {
            const int kb = kc * 32 + qp * 4;   // byte offset of k pair
            uint32_t a[2][4];
            #pragma unroll
            for (int mc = 0; mc < 2; mc++) {
                const unsigned char* ap = As + (32 * mi + 16 * mc + g) * PADB + kb;
                a[mc][0] = *(const uint32_t*)(ap);
                a[mc][1] = *(const uint32_t*)(ap + 8 * PADB);
                a[mc][2] = *(const uint32_t*)(ap + 16);
                a[mc][3] = *(const uint32_t*)(ap + 8 * PADB + 16);
            }
            #pragma unroll
            for (int nc = 0; nc < 8; nc++) {
                const unsigned char* bp = Bs + (64 * nj + 8 * nc + g) * PADB + kb;
                const uint32_t b0 = *(const uint32_t*)(bp);
                const uint32_t b1r = *(const uint32_t*)(bp + 16);
                mma16816(acc[0][nc], a[0], b0, b1r);
                mma16816(acc[1][nc], a[1], b0, b1r);
            }
        }
    }

    // ---- Epilogue: partial q over this warp's 64 features ----
    const float* b1s = (const float*)(smem + SM_B1);
    const float* w2s = (const float*)(smem + SM_W2);
    float* red = (float*)(smem + SM_RED);   // [2][128]
    #pragma unroll
    for (int mc = 0; mc < 2; mc++) {
        #pragma unroll
        for (int rh = 0; rh < 2; rh++) {
            float s = 0.0f;
            #pragma unroll
            for (int nc = 0; nc < 8; nc++) {
                const int f0 = 64 * nj + 8 * nc + 2 * qp;
                const float h0 = acc[mc][nc][2 * rh]     + b1s[f0];
                const float h1 = acc[mc][nc][2 * rh + 1] + b1s[f0 + 1];
                s += silu_f(h0) * w2s[f0] + silu_f(h1) * w2s[f0 + 1];
            }
            s += __shfl_xor_sync(0xffffffffu, s, 1);
            s += __shfl_xor_sync(0xffffffffu, s, 2);
            if (qp == 0)
                red[nj * 128 + 32 * mi + 16 * mc + 8 * rh + g] = s;
        }
    }
    __syncthreads();
    if (tid < 128 && base + tid < n_nodes) {
        const float sum = red[tid] + red[128 + tid];
        q_dev[base + tid] = silu_f(sum + b2[0]);
    }
}

// ---------- Kernel 2: edge pass, 4 edges/thread, vectorized LSU traffic ----
__global__ void __launch_bounds__(256)
edge_kernel4(const float4* __restrict__ rij4, const float4* __restrict__ vij4,
             const int4* __restrict__ src4, const int4* __restrict__ dst4,
             int n_quads) {
    const int i = blockIdx.x * blockDim.x + threadIdx.x;
    if (i >= n_quads) return;

    const float4 r = rij4[i];
    const int4   s = src4[i];
    const int4   d = dst4[i];
    const float4 a = vij4[(size_t)3 * i];
    const float4 b = vij4[(size_t)3 * i + 1];
    const float4 c = vij4[(size_t)3 * i + 2];

    const float k = 3.14159265358979323846f / RCUT;
    float c0 = 0.5f * (__cosf(r.x * k) + 1.0f); if (r.x >= RCUT) c0 = 0.0f;
    float c1 = 0.5f * (__cosf(r.y * k) + 1.0f); if (r.y >= RCUT) c1 = 0.0f;
    float c2 = 0.5f * (__cosf(r.z * k) + 1.0f); if (r.z >= RCUT) c2 = 0.0f;
    float c3 = 0.5f * (__cosf(r.w * k) + 1.0f); if (r.w >= RCUT) c3 = 0.0f;

    const float s0 = __ldg(&q_dev[s.x]) * c0;
    const float s1 = __ldg(&q_dev[s.y]) * c1;
    const float s2 = __ldg(&q_dev[s.z]) * c2;
    const float s3 = __ldg(&q_dev[s.w]) * c3;

    atomicAdd(&mu4_dev[d.x], make_float4(a.x * s0, a.y * s0, a.z * s0, 0.0f));
    atomicAdd(&mu4_dev[d.y], make_float4(a.w * s1, b.x * s1, b.y * s1, 0.0f));
    atomicAdd(&mu4_dev[d.z], make_float4(b.z * s2, b.w * s2, c.x * s2, 0.0f));
    atomicAdd(&mu4_dev[d.w], make_float4(c.y * s3, c.z * s3, c.w * s3, 0.0f));
}

// ---------- Kernel 3: compact [N,4] scratch -> [N,3] output, 4 nodes/thread --
__global__ void copy_kernel4(float4* __restrict__ out4, int n_quads) {
    const int i = blockIdx.x * blockDim.x + threadIdx.x;
    if (i >= n_quads) return;
    const float4 m0 = mu4_dev[4 * i];
    const float4 m1 = mu4_dev[4 * i + 1];
    const float4 m2 = mu4_dev[4 * i + 2];
    const float4 m3 = mu4_dev[4 * i + 3];
    out4[3 * i]     = make_float4(m0.x, m0.y, m0.z, m1.x);
    out4[3 * i + 1] = make_float4(m1.y, m1.z, m2.x, m2.y);
    out4[3 * i + 2] = make_float4(m2.z, m3.x, m3.y, m3.z);
}

extern "C" void kernel_launch(void* const* d_in, const int* in_sizes, int n_in,
                              void* d_out, int out_size) {
    const float* x   = (const float*)d_in[0];
    const float* rij = (const float*)d_in[1];
    const float* vij = (const float*)d_in[2];
    const int*   src = (const int*)d_in[3];
    const int*   dst = (const int*)d_in[4];
    const float* W1  = (const float*)d_in[5];
    const float* b1  = (const float*)d_in[6];
    const float* W2  = (const float*)d_in[7];
    const float* b2  = (const float*)d_in[8];
    float* out = (float*)d_out;

    const int n_nodes = in_sizes[0] / F;   // 100000
    const int n_edges = in_sizes[1];       // 6400000

    cudaFuncSetAttribute(node_q_kernel,
                         cudaFuncAttributeMaxDynamicSharedMemorySize, SM_TOT);

    prep_B_kernel<<<16, 128>>>(W1);

    const int n_tiles = (n_nodes + 127) / 128;   // 782
    node_q_kernel<<<n_tiles, 256, SM_TOT>>>(x, b1, W2, b2, n_nodes);

    const int eq = n_edges / 4;            // 1,600,000 (exact)
    edge_kernel4<<<(eq + 255) / 256, 256>>>((const float4*)rij, (const float4*)vij,
                                            (const int4*)src, (const int4*)dst, eq);

    const int nq = n_nodes / 4;            // 25,000 (exact)
    copy_kernel4<<<(nq + 255) / 256, 256>>>((float4*)out, nq);
}

// round 12
// speedup vs baseline: 1.6684x; 1.2162x over previous
#include <cuda_runtime.h>
#include <cuda_bf16.h>
#include <cstdint>

#define F 128
#define RCUT 5.0f
#define MAX_NODES 100000

// Scratch (allocation-free rule: __device__ globals)
__device__ float  q_dev[MAX_NODES];
__device__ float4 mu4_dev[MAX_NODES];
// Transposed split-bf16 W1 images: W1T[f][k], dense [128][128] bf16
__device__ __align__(16) unsigned char W1T_hi[32768];
__device__ __align__(16) unsigned char W1T_lo[32768];

static __device__ __forceinline__ float silu_f(float z) {
    return __fdividef(z, 1.0f + __expf(-z));
}
static __device__ __forceinline__ uint32_t bpack(__nv_bfloat16 lo, __nv_bfloat16 hi) {
    return (uint32_t)__bfloat16_as_ushort(lo) | ((uint32_t)__bfloat16_as_ushort(hi) << 16);
}
static __device__ __forceinline__ uint32_t smem_u32(const void* p) {
    uint32_t a;
    asm("{ .reg .u64 t; cvta.to.shared.u64 t, %1; cvt.u32.u64 %0, t; }" : "=r"(a) : "l"(p));
    return a;
}

// warp-level bf16 MMA, baseline ISA (works on plain sm_103 target)
static __device__ __forceinline__ void mma16816(float* d, const uint32_t* a,
                                                uint32_t b0, uint32_t b1) {
    asm volatile(
        "mma.sync.aligned.m16n8k16.row.col.f32.bf16.bf16.f32 "
        "{%0,%1,%2,%3}, {%4,%5,%6,%7}, {%8,%9}, {%0,%1,%2,%3};"
        : "+f"(d[0]), "+f"(d[1]), "+f"(d[2]), "+f"(d[3])
        : "r"(a[0]), "r"(a[1]), "r"(a[2]), "r"(a[3]), "r"(b0), "r"(b1));
}
static __device__ __forceinline__ void ldsm4(uint32_t* r, uint32_t addr) {
    asm volatile("ldmatrix.sync.aligned.m8n8.x4.shared.b16 {%0,%1,%2,%3}, [%4];"
                 : "=r"(r[0]), "=r"(r[1]), "=r"(r[2]), "=r"(r[3]) : "r"(addr));
}

// ---------- Kernel 0: W1 -> transposed split-bf16 images ----------
__global__ void prep_B_kernel(const float* __restrict__ W1) {
    const int f = threadIdx.x;
    const int b = blockIdx.x;
    uint32_t hi[4], lo[4];
    #pragma unroll
    for (int j = 0; j < 4; j++) {
        const float w0 = W1[(8 * b + 2 * j)     * F + f];
        const float w1 = W1[(8 * b + 2 * j + 1) * F + f];
        const __nv_bfloat16 h0 = __float2bfloat16_rn(w0);
        const __nv_bfloat16 h1 = __float2bfloat16_rn(w1);
        const __nv_bfloat16 l0 = __float2bfloat16_rn(w0 - __bfloat162float(h0));
        const __nv_bfloat16 l1 = __float2bfloat16_rn(w1 - __bfloat162float(h1));
        hi[j] = bpack(h0, h1);
        lo[j] = bpack(l0, l1);
    }
    *(uint4*)(W1T_hi + f * 256 + b * 16) = make_uint4(hi[0], hi[1], hi[2], hi[3]);
    *(uint4*)(W1T_lo + f * 256 + b * 16) = make_uint4(lo[0], lo[1], lo[2], lo[3]);
}

// ---------- Kernel 1: node MLP, fused 3-term split-bf16 mma.sync ----------
// CTA = 256 thr / 8 warps, 64 nodes -> 2 CTAs/SM. Warp (mi = wid&1, nj = wid>>1)
// = 32-node x 32-feature tile. Fragments via ldmatrix.x4 (mapping identical to
// the verified R10 scalar loads). Fused k-loop issues xh@Wh + xl@Wh + xh@Wl
// per kc with frags loaded once.
#define PADB 272
#define SM_AH  0
#define SM_AL  17408
#define SM_BH  34816
#define SM_BL  69632
#define SM_B1  104448
#define SM_W2  104960
#define SM_RED 105472
#define SM_TOT 106496

__global__ void __launch_bounds__(256, 2)
node_q_kernel(const float* __restrict__ x, const float* __restrict__ b1,
              const float* __restrict__ W2, const float* __restrict__ b2,
              int n_nodes) {
    extern __shared__ __align__(16) unsigned char smem[];
    const uint32_t sb = smem_u32(smem);
    const int tid  = threadIdx.x;
    const int wid  = tid >> 5;
    const int lane = tid & 31;
    const int g    = lane >> 2;
    const int qp   = lane & 3;
    const int mi   = wid & 1;     // 32-node subtile
    const int nj   = wid >> 1;    // 32-feature subtile
    const int base = blockIdx.x * 64;

    // Zero accumulation scratch (edge kernel is ordered after us)
    for (int i = blockIdx.x * 256 + tid; i < n_nodes; i += gridDim.x * 256)
        mu4_dev[i] = make_float4(0.f, 0.f, 0.f, 0.f);

    // ---- Stage x tile (64 rows) -> split bf16, padded rows ----
    for (int i = tid; i < 2048; i += 256) {
        const int row = i >> 5;
        const int c4  = i & 31;
        const int col = 4 * c4;
        float4 v = make_float4(0.f, 0.f, 0.f, 0.f);
        if (base + row < n_nodes)
            v = ((const float4*)(x + (size_t)(base + row) * F))[c4];
        const __nv_bfloat16 h0 = __float2bfloat16_rn(v.x);
        const __nv_bfloat16 h1 = __float2bfloat16_rn(v.y);
        const __nv_bfloat16 h2 = __float2bfloat16_rn(v.z);
        const __nv_bfloat16 h3 = __float2bfloat16_rn(v.w);
        const __nv_bfloat16 l0 = __float2bfloat16_rn(v.x - __bfloat162float(h0));
        const __nv_bfloat16 l1 = __float2bfloat16_rn(v.y - __bfloat162float(h1));
        const __nv_bfloat16 l2 = __float2bfloat16_rn(v.z - __bfloat162float(h2));
        const __nv_bfloat16 l3 = __float2bfloat16_rn(v.w - __bfloat162float(h3));
        const int off = row * PADB + col * 2;
        *(uint2*)(smem + SM_AH + off) = make_uint2(bpack(h0, h1), bpack(h2, h3));
        *(uint2*)(smem + SM_AL + off) = make_uint2(bpack(l0, l1), bpack(l2, l3));
    }
    // ---- Copy W1T images (128 rows) into padded smem ----
    for (int i = tid; i < 4096; i += 256) {
        const int row = i >> 5;
        const int c4  = i & 31;
        const int goff = row * 256 + c4 * 8;
        const int soff = row * PADB + c4 * 8;
        *(uint2*)(smem + SM_BH + soff) = *(const uint2*)(W1T_hi + goff);
        *(uint2*)(smem + SM_BL + soff) = *(const uint2*)(W1T_lo + goff);
    }
    if (tid < 128) {
        ((float*)(smem + SM_B1))[tid] = b1[tid];
        ((float*)(smem + SM_W2))[tid] = W2[tid];
    }
    __syncthreads();

    // ldmatrix per-thread row/col offsets (byte offsets within a tile)
    const int lr  = lane & 7;
    // A: mat0..3 = (rows+0,kb) (rows+8,kb) (rows+0,kb+16) (rows+8,kb+16)
    const uint32_t aoff = (uint32_t)(32 * mi + lr + 8 * ((lane >> 3) & 1)) * PADB
                        + 16 * (lane >> 4);
    // B: mat0..3 = (n+0,kb) (n+0,kb+16) (n+8,kb) (n+8,kb+16)  -> frags for 2 nc
    const uint32_t boff = (uint32_t)(32 * nj + lr + 8 * (lane >> 4)) * PADB
                        + 16 * ((lane >> 3) & 1);

    float acc[2][4][4];
    #pragma unroll
    for (int mc = 0; mc < 2; mc++)
        #pragma unroll
        for (int nc = 0; nc < 4; nc++)
            #pragma unroll
            for (int r = 0; r < 4; r++) acc[mc][nc][r] = 0.0f;

    #pragma unroll
    for (int kc = 0; kc < 8; kc++) {
        const uint32_t kb = kc * 32;
        uint32_t ah[2][4], al[2][4];
        ldsm4(ah[0], sb + SM_AH + aoff + kb);
        ldsm4(ah[1], sb + SM_AH + aoff + 16 * PADB + kb);
        ldsm4(al[0], sb + SM_AL + aoff + kb);
        ldsm4(al[1], sb + SM_AL + aoff + 16 * PADB + kb);
        #pragma unroll
        for (int c = 0; c < 2; c++) {           // nc pair
            uint32_t bh[4], bl[4];
            ldsm4(bh, sb + SM_BH + boff + c * 16 * PADB + kb);
            ldsm4(bl, sb + SM_BL + boff + c * 16 * PADB + kb);
            #pragma unroll
            for (int h = 0; h < 2; h++) {       // nc = 2c + h, frags bh[2h],bh[2h+1]
                const int nc = 2 * c + h;
                #pragma unroll
                for (int mc = 0; mc < 2; mc++) {
                    mma16816(acc[mc][nc], ah[mc], bh[2 * h], bh[2 * h + 1]); // xh@Wh
                    mma16816(acc[mc][nc], al[mc], bh[2 * h], bh[2 * h + 1]); // xl@Wh
                    mma16816(acc[mc][nc], ah[mc], bl[2 * h], bl[2 * h + 1]); // xh@Wl
                }
            }
        }
    }

    // ---- Epilogue: partial q over this warp's 32 features ----
    const float* b1s = (const float*)(smem + SM_B1);
    const float* w2s = (const float*)(smem + SM_W2);
    float* red = (float*)(smem + SM_RED);   // [4 nj][64 rows]
    #pragma unroll
    for (int mc = 0; mc < 2; mc++) {
        #pragma unroll
        for (int rh = 0; rh < 2; rh++) {
            float s = 0.0f;
            #pragma unroll
            for (int nc = 0; nc < 4; nc++) {
                const int f0 = 32 * nj + 8 * nc + 2 * qp;
                const float h0 = acc[mc][nc][2 * rh]     + b1s[f0];
                const float h1 = acc[mc][nc][2 * rh + 1] + b1s[f0 + 1];
                s += silu_f(h0) * w2s[f0] + silu_f(h1) * w2s[f0 + 1];
            }
            s += __shfl_xor_sync(0xffffffffu, s, 1);
            s += __shfl_xor_sync(0xffffffffu, s, 2);
            if (qp == 0)
                red[nj * 64 + 32 * mi + 16 * mc + 8 * rh + g] = s;
        }
    }
    __syncthreads();
    if (tid < 64 && base + tid < n_nodes) {
        const float sum = (red[tid] + red[64 + tid]) + (red[128 + tid] + red[192 + tid]);
        q_dev[base + tid] = silu_f(sum + b2[0]);
    }
}

// ---------- Kernel 2: edge pass, 4 edges/thread, vectorized LSU traffic ----
__global__ void __launch_bounds__(256)
edge_kernel4(const float4* __restrict__ rij4, const float4* __restrict__ vij4,
             const int4* __restrict__ src4, const int4* __restrict__ dst4,
             int n_quads) {
    const int i = blockIdx.x * blockDim.x + threadIdx.x;
    if (i >= n_quads) return;

    const float4 r = rij4[i];
    const int4   s = src4[i];
    const int4   d = dst4[i];
    const float4 a = vij4[(size_t)3 * i];
    const float4 b = vij4[(size_t)3 * i + 1];
    const float4 c = vij4[(size_t)3 * i + 2];

    const float k = 3.14159265358979323846f / RCUT;
    float c0 = 0.5f * (__cosf(r.x * k) + 1.0f); if (r.x >= RCUT) c0 = 0.0f;
    float c1 = 0.5f * (__cosf(r.y * k) + 1.0f); if (r.y >= RCUT) c1 = 0.0f;
    float c2 = 0.5f * (__cosf(r.z * k) + 1.0f); if (r.z >= RCUT) c2 = 0.0f;
    float c3 = 0.5f * (__cosf(r.w * k) + 1.0f); if (r.w >= RCUT) c3 = 0.0f;

    const float s0 = __ldg(&q_dev[s.x]) * c0;
    const float s1 = __ldg(&q_dev[s.y]) * c1;
    const float s2 = __ldg(&q_dev[s.z]) * c2;
    const float s3 = __ldg(&q_dev[s.w]) * c3;

    atomicAdd(&mu4_dev[d.x], make_float4(a.x * s0, a.y * s0, a.z * s0, 0.0f));
    atomicAdd(&mu4_dev[d.y], make_float4(a.w * s1, b.x * s1, b.y * s1, 0.0f));
    atomicAdd(&mu4_dev[d.z], make_float4(b.z * s2, b.w * s2, c.x * s2, 0.0f));
    atomicAdd(&mu4_dev[d.w], make_float4(c.y * s3, c.z * s3, c.w * s3, 0.0f));
}

// ---------- Kernel 3: compact [N,4] scratch -> [N,3] output, 4 nodes/thread --
__global__ void copy_kernel4(float4* __restrict__ out4, int n_quads) {
    const int i = blockIdx.x * blockDim.x + threadIdx.x;
    if (i >= n_quads) return;
    const float4 m0 = mu4_dev[4 * i];
    const float4 m1 = mu4_dev[4 * i + 1];
    const float4 m2 = mu4_dev[4 * i + 2];
    const float4 m3 = mu4_dev[4 * i + 3];
    out4[3 * i]     = make_float4(m0.x, m0.y, m0.z, m1.x);
    out4[3 * i + 1] = make_float4(m1.y, m1.z, m2.x, m2.y);
    out4[3 * i + 2] = make_float4(m2.z, m3.x, m3.y, m3.z);
}

extern "C" void kernel_launch(void* const* d_in, const int* in_sizes, int n_in,
                              void* d_out, int out_size) {
    const float* x   = (const float*)d_in[0];
    const float* rij = (const float*)d_in[1];
    const float* vij = (const float*)d_in[2];
    const int*   src = (const int*)d_in[3];
    const int*   dst = (const int*)d_in[4];
    const float* W1  = (const float*)d_in[5];
    const float* b1  = (const float*)d_in[6];
    const float* W2  = (const float*)d_in[7];
    const float* b2  = (const float*)d_in[8];
    float* out = (float*)d_out;

    const int n_nodes = in_sizes[0] / F;   // 100000
    const int n_edges = in_sizes[1];       // 6400000

    cudaFuncSetAttribute(node_q_kernel,
                         cudaFuncAttributeMaxDynamicSharedMemorySize, SM_TOT);

    prep_B_kernel<<<16, 128>>>(W1);

    const int n_tiles = (n_nodes + 63) / 64;   // 1563
    node_q_kernel<<<n_tiles, 256, SM_TOT>>>(x, b1, W2, b2, n_nodes);

    const int eq = n_edges / 4;            // 1,600,000 (exact)
    edge_kernel4<<<(eq + 255) / 256, 256>>>((const float4*)rij, (const float4*)vij,
                                            (const int4*)src, (const int4*)dst, eq);

    const int nq = n_nodes / 4;            // 25,000 (exact)
    copy_kernel4<<<(nq + 255) / 256, 256>>>((float4*)out, nq);
}

// round 13
// speedup vs baseline: 2.2811x; 1.3672x over previous
#include <cuda_runtime.h>
#include <cuda_bf16.h>
#include <cstdint>

#define F 128
#define RCUT 5.0f
#define MAX_NODES 100000
#define NODE_GRID 296

// Scratch (allocation-free rule: __device__ globals)
__device__ float  q_dev[MAX_NODES];
__device__ float4 mu4_dev[MAX_NODES];
// Transposed split-bf16 W1 images: W1T[f][k], dense [128][128] bf16
__device__ __align__(16) unsigned char W1T_hi[32768];
__device__ __align__(16) unsigned char W1T_lo[32768];

static __device__ __forceinline__ float silu_f(float z) {
    return __fdividef(z, 1.0f + __expf(-z));
}
static __device__ __forceinline__ uint32_t bpack(__nv_bfloat16 lo, __nv_bfloat16 hi) {
    return (uint32_t)__bfloat16_as_ushort(lo) | ((uint32_t)__bfloat16_as_ushort(hi) << 16);
}
static __device__ __forceinline__ uint32_t smem_u32(const void* p) {
    uint32_t a;
    asm("{ .reg .u64 t; cvta.to.shared.u64 t, %1; cvt.u32.u64 %0, t; }" : "=r"(a) : "l"(p));
    return a;
}

// warp-level bf16 MMA, baseline ISA (works on plain sm_103 target)
static __device__ __forceinline__ void mma16816(float* d, const uint32_t* a,
                                                uint32_t b0, uint32_t b1) {
    asm volatile(
        "mma.sync.aligned.m16n8k16.row.col.f32.bf16.bf16.f32 "
        "{%0,%1,%2,%3}, {%4,%5,%6,%7}, {%8,%9}, {%0,%1,%2,%3};"
        : "+f"(d[0]), "+f"(d[1]), "+f"(d[2]), "+f"(d[3])
        : "r"(a[0]), "r"(a[1]), "r"(a[2]), "r"(a[3]), "r"(b0), "r"(b1));
}
static __device__ __forceinline__ void ldsm4(uint32_t* r, uint32_t addr) {
    asm volatile("ldmatrix.sync.aligned.m8n8.x4.shared.b16 {%0,%1,%2,%3}, [%4];"
                 : "=r"(r[0]), "=r"(r[1]), "=r"(r[2]), "=r"(r[3]) : "r"(addr));
}

// ---------- Kernel 0: W1 -> transposed split-bf16 images ----------
__global__ void prep_B_kernel(const float* __restrict__ W1) {
    const int f = threadIdx.x;
    const int b = blockIdx.x;
    uint32_t hi[4], lo[4];
    #pragma unroll
    for (int j = 0; j < 4; j++) {
        const float w0 = W1[(8 * b + 2 * j)     * F + f];
        const float w1 = W1[(8 * b + 2 * j + 1) * F + f];
        const __nv_bfloat16 h0 = __float2bfloat16_rn(w0);
        const __nv_bfloat16 h1 = __float2bfloat16_rn(w1);
        const __nv_bfloat16 l0 = __float2bfloat16_rn(w0 - __bfloat162float(h0));
        const __nv_bfloat16 l1 = __float2bfloat16_rn(w1 - __bfloat162float(h1));
        hi[j] = bpack(h0, h1);
        lo[j] = bpack(l0, l1);
    }
    *(uint4*)(W1T_hi + f * 256 + b * 16) = make_uint4(hi[0], hi[1], hi[2], hi[3]);
    *(uint4*)(W1T_lo + f * 256 + b * 16) = make_uint4(lo[0], lo[1], lo[2], lo[3]);
}

// ---------- Kernel 1: persistent node MLP, pipelined split-bf16 mma.sync ----
// Grid = 296 persistent CTAs (2/SM), 256 thr / 8 warps, tile = 64 nodes.
// B (W1T hi/lo) staged ONCE per CTA. Per tile, next x is prefetched into
// registers while the current tile's MMA runs (single A buffer, 2 syncs/iter).
#define PADB 272
#define SM_AH  0
#define SM_AL  17408
#define SM_BH  34816
#define SM_BL  69632
#define SM_B1  104448
#define SM_W2  104960
#define SM_RED 105472
#define SM_TOT 106496

static __device__ __forceinline__ void load_xtile(float4* xreg, const float* __restrict__ x,
                                                  int tile, int n_tiles, int n_nodes, int tid) {
    const int base = tile * 64;
    #pragma unroll
    for (int j = 0; j < 8; j++) {
        const int i   = tid + j * 256;
        const int row = i >> 5;
        const int c4  = i & 31;
        xreg[j] = make_float4(0.f, 0.f, 0.f, 0.f);
        if (tile < n_tiles && base + row < n_nodes)
            xreg[j] = ((const float4*)(x + (size_t)(base + row) * F))[c4];
    }
}
static __device__ __forceinline__ void store_xtile(unsigned char* smem, const float4* xreg,
                                                   int tid) {
    #pragma unroll
    for (int j = 0; j < 8; j++) {
        const int i   = tid + j * 256;
        const int row = i >> 5;
        const int col = 4 * (i & 31);
        const float4 v = xreg[j];
        const __nv_bfloat16 h0 = __float2bfloat16_rn(v.x);
        const __nv_bfloat16 h1 = __float2bfloat16_rn(v.y);
        const __nv_bfloat16 h2 = __float2bfloat16_rn(v.z);
        const __nv_bfloat16 h3 = __float2bfloat16_rn(v.w);
        const __nv_bfloat16 l0 = __float2bfloat16_rn(v.x - __bfloat162float(h0));
        const __nv_bfloat16 l1 = __float2bfloat16_rn(v.y - __bfloat162float(h1));
        const __nv_bfloat16 l2 = __float2bfloat16_rn(v.z - __bfloat162float(h2));
        const __nv_bfloat16 l3 = __float2bfloat16_rn(v.w - __bfloat162float(h3));
        const int off = row * PADB + col * 2;
        *(uint2*)(smem + SM_AH + off) = make_uint2(bpack(h0, h1), bpack(h2, h3));
        *(uint2*)(smem + SM_AL + off) = make_uint2(bpack(l0, l1), bpack(l2, l3));
    }
}

__global__ void __launch_bounds__(256, 2)
node_q_kernel(const float* __restrict__ x, const float* __restrict__ b1,
              const float* __restrict__ W2, const float* __restrict__ b2,
              int n_nodes) {
    extern __shared__ __align__(16) unsigned char smem[];
    const uint32_t sb = smem_u32(smem);
    const int tid  = threadIdx.x;
    const int wid  = tid >> 5;
    const int lane = tid & 31;
    const int g    = lane >> 2;
    const int qp   = lane & 3;
    const int mi   = wid & 1;     // 32-node subtile
    const int nj   = wid >> 1;    // 32-feature subtile
    const int n_tiles = (n_nodes + 63) / 64;

    // Zero accumulation scratch (edge kernel is ordered after us)
    for (int i = blockIdx.x * 256 + tid; i < n_nodes; i += NODE_GRID * 256)
        mu4_dev[i] = make_float4(0.f, 0.f, 0.f, 0.f);

    // ---- Stage B images ONCE per CTA ----
    for (int i = tid; i < 4096; i += 256) {
        const int row = i >> 5;
        const int c4  = i & 31;
        const int goff = row * 256 + c4 * 8;
        const int soff = row * PADB + c4 * 8;
        *(uint2*)(smem + SM_BH + soff) = *(const uint2*)(W1T_hi + goff);
        *(uint2*)(smem + SM_BL + soff) = *(const uint2*)(W1T_lo + goff);
    }
    if (tid < 128) {
        ((float*)(smem + SM_B1))[tid] = b1[tid];
        ((float*)(smem + SM_W2))[tid] = W2[tid];
    }

    // ldmatrix per-thread offsets
    const int lr = lane & 7;
    const uint32_t aoff = (uint32_t)(32 * mi + lr + 8 * ((lane >> 3) & 1)) * PADB
                        + 16 * (lane >> 4);
    const uint32_t boff = (uint32_t)(32 * nj + lr + 8 * (lane >> 4)) * PADB
                        + 16 * ((lane >> 3) & 1);

    const float* b1s = (const float*)(smem + SM_B1);
    const float* w2s = (const float*)(smem + SM_W2);
    float* red = (float*)(smem + SM_RED);   // [4 nj][64 rows]
    const float b2v = b2[0];

    // ---- Pipeline prologue ----
    float4 xreg[8];
    int t = blockIdx.x;
    load_xtile(xreg, x, t, n_tiles, n_nodes, tid);
    store_xtile(smem, xreg, tid);
    load_xtile(xreg, x, t + NODE_GRID, n_tiles, n_nodes, tid);
    __syncthreads();

    for (; t < n_tiles; t += NODE_GRID) {
        // ---- Fused 3-term MMA over current A tile ----
        float acc[2][4][4];
        #pragma unroll
        for (int mc = 0; mc < 2; mc++)
            #pragma unroll
            for (int nc = 0; nc < 4; nc++)
                #pragma unroll
                for (int r = 0; r < 4; r++) acc[mc][nc][r] = 0.0f;

        #pragma unroll
        for (int kc = 0; kc < 8; kc++) {
            const uint32_t kb = kc * 32;
            uint32_t ah[2][4], al[2][4];
            ldsm4(ah[0], sb + SM_AH + aoff + kb);
            ldsm4(ah[1], sb + SM_AH + aoff + 16 * PADB + kb);
            ldsm4(al[0], sb + SM_AL + aoff + kb);
            ldsm4(al[1], sb + SM_AL + aoff + 16 * PADB + kb);
            #pragma unroll
            for (int c = 0; c < 2; c++) {
                uint32_t bh[4], bl[4];
                ldsm4(bh, sb + SM_BH + boff + c * 16 * PADB + kb);
                ldsm4(bl, sb + SM_BL + boff + c * 16 * PADB + kb);
                #pragma unroll
                for (int h = 0; h < 2; h++) {
                    const int nc = 2 * c + h;
                    #pragma unroll
                    for (int mc = 0; mc < 2; mc++) {
                        mma16816(acc[mc][nc], ah[mc], bh[2 * h], bh[2 * h + 1]); // xh@Wh
                        mma16816(acc[mc][nc], al[mc], bh[2 * h], bh[2 * h + 1]); // xl@Wh
                        mma16816(acc[mc][nc], ah[mc], bl[2 * h], bl[2 * h + 1]); // xh@Wl
                    }
                }
            }
        }

        // ---- Epilogue: partial q over this warp's 32 features ----
        #pragma unroll
        for (int mc = 0; mc < 2; mc++) {
            #pragma unroll
            for (int rh = 0; rh < 2; rh++) {
                float s = 0.0f;
                #pragma unroll
                for (int nc = 0; nc < 4; nc++) {
                    const int f0 = 32 * nj + 8 * nc + 2 * qp;
                    const float h0 = acc[mc][nc][2 * rh]     + b1s[f0];
                    const float h1 = acc[mc][nc][2 * rh + 1] + b1s[f0 + 1];
                    s += silu_f(h0) * w2s[f0] + silu_f(h1) * w2s[f0 + 1];
                }
                s += __shfl_xor_sync(0xffffffffu, s, 1);
                s += __shfl_xor_sync(0xffffffffu, s, 2);
                if (qp == 0)
                    red[nj * 64 + 32 * mi + 16 * mc + 8 * rh + g] = s;
            }
        }
        __syncthreads();   // red ready; all warps done reading A
        const int base = t * 64;
        if (tid < 64 && base + tid < n_nodes) {
            const float sum = (red[tid] + red[64 + tid]) + (red[128 + tid] + red[192 + tid]);
            q_dev[base + tid] = silu_f(sum + b2v);
        }

        // ---- Stage next tile (regs -> smem), prefetch tile after next ----
        store_xtile(smem, xreg, tid);
        load_xtile(xreg, x, t + 2 * NODE_GRID, n_tiles, n_nodes, tid);
        __syncthreads();   // A(t+G) ready; red consumed
    }
}

// ---------- Kernel 2: edge pass, 4 edges/thread, vectorized LSU traffic ----
__global__ void __launch_bounds__(256)
edge_kernel4(const float4* __restrict__ rij4, const float4* __restrict__ vij4,
             const int4* __restrict__ src4, const int4* __restrict__ dst4,
             int n_quads) {
    const int i = blockIdx.x * blockDim.x + threadIdx.x;
    if (i >= n_quads) return;

    const float4 r = rij4[i];
    const int4   s = src4[i];
    const int4   d = dst4[i];
    const float4 a = vij4[(size_t)3 * i];
    const float4 b = vij4[(size_t)3 * i + 1];
    const float4 c = vij4[(size_t)3 * i + 2];

    const float k = 3.14159265358979323846f / RCUT;
    float c0 = 0.5f * (__cosf(r.x * k) + 1.0f); if (r.x >= RCUT) c0 = 0.0f;
    float c1 = 0.5f * (__cosf(r.y * k) + 1.0f); if (r.y >= RCUT) c1 = 0.0f;
    float c2 = 0.5f * (__cosf(r.z * k) + 1.0f); if (r.z >= RCUT) c2 = 0.0f;
    float c3 = 0.5f * (__cosf(r.w * k) + 1.0f); if (r.w >= RCUT) c3 = 0.0f;

    const float s0 = __ldg(&q_dev[s.x]) * c0;
    const float s1 = __ldg(&q_dev[s.y]) * c1;
    const float s2 = __ldg(&q_dev[s.z]) * c2;
    const float s3 = __ldg(&q_dev[s.w]) * c3;

    atomicAdd(&mu4_dev[d.x], make_float4(a.x * s0, a.y * s0, a.z * s0, 0.0f));
    atomicAdd(&mu4_dev[d.y], make_float4(a.w * s1, b.x * s1, b.y * s1, 0.0f));
    atomicAdd(&mu4_dev[d.z], make_float4(b.z * s2, b.w * s2, c.x * s2, 0.0f));
    atomicAdd(&mu4_dev[d.w], make_float4(c.y * s3, c.z * s3, c.w * s3, 0.0f));
}

// ---------- Kernel 3: compact [N,4] scratch -> [N,3] output, 4 nodes/thread --
__global__ void copy_kernel4(float4* __restrict__ out4, int n_quads) {
    const int i = blockIdx.x * blockDim.x + threadIdx.x;
    if (i >= n_quads) return;
    const float4 m0 = mu4_dev[4 * i];
    const float4 m1 = mu4_dev[4 * i + 1];
    const float4 m2 = mu4_dev[4 * i + 2];
    const float4 m3 = mu4_dev[4 * i + 3];
    out4[3 * i]     = make_float4(m0.x, m0.y, m0.z, m1.x);
    out4[3 * i + 1] = make_float4(m1.y, m1.z, m2.x, m2.y);
    out4[3 * i + 2] = make_float4(m2.z, m3.x, m3.y, m3.z);
}

extern "C" void kernel_launch(void* const* d_in, const int* in_sizes, int n_in,
                              void* d_out, int out_size) {
    const float* x   = (const float*)d_in[0];
    const float* rij = (const float*)d_in[1];
    const float* vij = (const float*)d_in[2];
    const int*   src = (const int*)d_in[3];
    const int*   dst = (const int*)d_in[4];
    const float* W1  = (const float*)d_in[5];
    const float* b1  = (const float*)d_in[6];
    const float* W2  = (const float*)d_in[7];
    const float* b2  = (const float*)d_in[8];
    float* out = (float*)d_out;

    const int n_nodes = in_sizes[0] / F;   // 100000
    const int n_edges = in_sizes[1];       // 6400000

    cudaFuncSetAttribute(node_q_kernel,
                         cudaFuncAttributeMaxDynamicSharedMemorySize, SM_TOT);

    prep_B_kernel<<<16, 128>>>(W1);

    node_q_kernel<<<NODE_GRID, 256, SM_TOT>>>(x, b1, W2, b2, n_nodes);

    const int eq = n_edges / 4;            // 1,600,000 (exact)
    edge_kernel4<<<(eq + 255) / 256, 256>>>((const float4*)rij, (const float4*)vij,
                                            (const int4*)src, (const int4*)dst, eq);

    const int nq = n_nodes / 4;            // 25,000 (exact)
    copy_kernel4<<<(nq + 255) / 256, 256>>>((float4*)out, nq);
}